// round 3
// baseline (speedup 1.0000x reference)
#include <cuda_runtime.h>
#include <math.h>

// Problem constants
#define BB 8
#define NN 1024
#define DD 768
#define HH 12
#define YY 64
#define MM 3072
#define STEPS 12
#define ALPHA 0.1f
#define EPS_LN 1e-5f
#define BETA_ATT 0.125f   // 1/sqrt(64)

#define BN_TOK (BB*NN)            // 8192
#define GSZ    (BB*NN*DD)         // 6291456
#define PSZ    ((long)BB*HH*NN*NN) // 100663296
#define RSZ    (BB*NN*MM)         // 25165824

// Scratch (static __device__ arrays: the sanctioned alloc-free workaround)
__device__ float d_g[GSZ];
__device__ float d_q[GSZ];
__device__ float d_k[GSZ];
__device__ float d_dq[GSZ];
__device__ float d_dk[GSZ];
__device__ float d_acc[GSZ];
__device__ float d_r[RSZ];
__device__ float d_P[PSZ];

// ---------------------------------------------------------------------------
// Generic tiled SGEMM:  C = (accum? C : 0) + scale * A*B   (optional relu)
//   A(m,k) at A[m*sa_m + k*sa_k];  B(k,n) at B[k*sb_k + n*sb_n];
//   C(m,n) at C[m*sc + n].
//   Batched via blockIdx.z: offset = (z/bdiv)*Out + (z%bdiv)*In per operand.
//   AKC: A contiguous along k.  BNC: B contiguous along n. (for coalescing)
//   All dims must be multiples of tile sizes (true for this problem).
// ---------------------------------------------------------------------------
template<bool AKC, bool BNC>
__global__ __launch_bounds__(256)
void sgemm(const float* __restrict__ Ag, const float* __restrict__ Bg,
           float* __restrict__ Cg,
           int Mdim, int Ndim, int Kdim,
           int sa_m, int sa_k, int sb_k, int sb_n, int sc,
           int bdiv,
           long aOut, long aIn, long bOut, long bIn, long cOut, long cIn,
           float scale, int relu, int accum)
{
    __shared__ float Asm[16][65];
    __shared__ float Bsm[16][65];

    const int z = blockIdx.z;
    const float* A = Ag + (long)(z / bdiv) * aOut + (long)(z % bdiv) * aIn;
    const float* B = Bg + (long)(z / bdiv) * bOut + (long)(z % bdiv) * bIn;
    float*       C = Cg + (long)(z / bdiv) * cOut + (long)(z % bdiv) * cIn;

    const int m0 = blockIdx.y * 64;
    const int n0 = blockIdx.x * 64;
    const int t  = threadIdx.x;
    const int tx = t & 15;
    const int ty = t >> 4;

    float c[4][4];
#pragma unroll
    for (int i = 0; i < 4; i++)
#pragma unroll
        for (int j = 0; j < 4; j++) c[i][j] = 0.f;

    for (int k0 = 0; k0 < Kdim; k0 += 16) {
        // Load A tile (64 rows x 16 k)
        if (AKC) {
#pragma unroll
            for (int e = 0; e < 4; e++) {
                int idx = t + e * 256;
                int i = idx >> 4, j = idx & 15;   // lanes vary j (k) fast: coalesced
                Asm[j][i] = A[(long)(m0 + i) * sa_m + (long)(k0 + j) * sa_k];
            }
        } else {
#pragma unroll
            for (int e = 0; e < 4; e++) {
                int idx = t + e * 256;
                int i = idx & 63, j = idx >> 6;   // lanes vary i (m) fast: coalesced
                Asm[j][i] = A[(long)(m0 + i) * sa_m + (long)(k0 + j) * sa_k];
            }
        }
        // Load B tile (16 k x 64 cols)
        if (BNC) {
#pragma unroll
            for (int e = 0; e < 4; e++) {
                int idx = t + e * 256;
                int n = idx & 63, kk = idx >> 6;  // lanes vary n fast: coalesced
                Bsm[kk][n] = B[(long)(k0 + kk) * sb_k + (long)(n0 + n) * sb_n];
            }
        } else {
#pragma unroll
            for (int e = 0; e < 4; e++) {
                int idx = t + e * 256;
                int kk = idx & 15, n = idx >> 4;  // lanes vary k fast: coalesced
                Bsm[kk][n] = B[(long)(k0 + kk) * sb_k + (long)(n0 + n) * sb_n];
            }
        }
        __syncthreads();

#pragma unroll
        for (int kk = 0; kk < 16; kk++) {
            float a[4], b[4];
#pragma unroll
            for (int i = 0; i < 4; i++) a[i] = Asm[kk][ty + 16 * i];
#pragma unroll
            for (int j = 0; j < 4; j++) b[j] = Bsm[kk][tx + 16 * j];
#pragma unroll
            for (int i = 0; i < 4; i++)
#pragma unroll
                for (int j = 0; j < 4; j++) c[i][j] = fmaf(a[i], b[j], c[i][j]);
        }
        __syncthreads();
    }

#pragma unroll
    for (int i = 0; i < 4; i++) {
        long rbase = (long)(m0 + ty + 16 * i) * sc + n0;
#pragma unroll
        for (int j = 0; j < 4; j++) {
            long cidx = rbase + tx + 16 * j;
            float v = c[i][j] * scale;
            if (accum) v += C[cidx];
            if (relu)  v = fmaxf(v, 0.f);
            C[cidx] = v;
        }
    }
}

// ---------------------------------------------------------------------------
// LayerNorm: one block per token row (768 elems, 256 threads * 3)
// ---------------------------------------------------------------------------
__global__ __launch_bounds__(256)
void layernorm_kernel(const float* __restrict__ x, const float* __restrict__ gamma,
                      const float* __restrict__ beta, float* __restrict__ g)
{
    const long base = (long)blockIdx.x * DD;
    const int t = threadIdx.x;
    float v[3];
    float s = 0.f, ss = 0.f;
#pragma unroll
    for (int i = 0; i < 3; i++) {
        v[i] = x[base + t + i * 256];
        s += v[i];
        ss = fmaf(v[i], v[i], ss);
    }
    // warp reduce
#pragma unroll
    for (int o = 16; o > 0; o >>= 1) {
        s  += __shfl_xor_sync(0xffffffffu, s, o);
        ss += __shfl_xor_sync(0xffffffffu, ss, o);
    }
    __shared__ float rs[8], rss[8], bc[2];
    if ((t & 31) == 0) { rs[t >> 5] = s; rss[t >> 5] = ss; }
    __syncthreads();
    if (t == 0) {
        float a = 0.f, b = 0.f;
#pragma unroll
        for (int i = 0; i < 8; i++) { a += rs[i]; b += rss[i]; }
        float mean = a * (1.f / DD);
        float var  = b * (1.f / DD) - mean * mean;
        bc[0] = mean;
        bc[1] = rsqrtf(var + EPS_LN);
    }
    __syncthreads();
    const float mean = bc[0], rinv = bc[1];
#pragma unroll
    for (int i = 0; i < 3; i++) {
        int col = t + i * 256;
        g[base + col] = gamma[col] * (v[i] - mean) * rinv + beta[col];
    }
}

// ---------------------------------------------------------------------------
// Row softmax over k (row length 1024), in place on P'
// ---------------------------------------------------------------------------
__global__ __launch_bounds__(256)
void softmax_kernel(float* __restrict__ P)
{
    const long base = (long)blockIdx.x * NN;
    const int t = threadIdx.x;
    float v[4];
#pragma unroll
    for (int i = 0; i < 4; i++) v[i] = P[base + t + i * 256];
    float m = fmaxf(fmaxf(v[0], v[1]), fmaxf(v[2], v[3]));
#pragma unroll
    for (int o = 16; o > 0; o >>= 1) m = fmaxf(m, __shfl_xor_sync(0xffffffffu, m, o));
    __shared__ float rm[8], rsum[8], bc[2];
    if ((t & 31) == 0) rm[t >> 5] = m;
    __syncthreads();
    if (t == 0) {
        float mm = rm[0];
#pragma unroll
        for (int i = 1; i < 8; i++) mm = fmaxf(mm, rm[i]);
        bc[0] = mm;
    }
    __syncthreads();
    const float rowmax = bc[0];
    float s = 0.f;
#pragma unroll
    for (int i = 0; i < 4; i++) { v[i] = __expf(v[i] - rowmax); s += v[i]; }
#pragma unroll
    for (int o = 16; o > 0; o >>= 1) s += __shfl_xor_sync(0xffffffffu, s, o);
    if ((t & 31) == 0) rsum[t >> 5] = s;
    __syncthreads();
    if (t == 0) {
        float a = 0.f;
#pragma unroll
        for (int i = 0; i < 8; i++) a += rsum[i];
        bc[1] = 1.f / a;
    }
    __syncthreads();
    const float inv = bc[1];
#pragma unroll
    for (int i = 0; i < 4; i++) P[base + t + i * 256] = v[i] * inv;
}

// ---------------------------------------------------------------------------
// x += ALPHA * acc
// ---------------------------------------------------------------------------
__global__ __launch_bounds__(256)
void update_kernel(float* __restrict__ x, const float* __restrict__ acc)
{
    long i = (long)blockIdx.x * 256 + threadIdx.x;
    x[i] = fmaf(ALPHA, acc[i], x[i]);
}

// ---------------------------------------------------------------------------
extern "C" void kernel_launch(void* const* d_in, const int* in_sizes, int n_in,
                              void* d_out, int out_size)
{
    const float* x_in  = (const float*)d_in[0];
    const float* gamma = (const float*)d_in[1];
    const float* betaL = (const float*)d_in[2];
    const float* Wq    = (const float*)d_in[3];  // [H,Y,D] -> [768,768] row-major (hy, d)
    const float* Wk    = (const float*)d_in[4];
    const float* xi    = (const float*)d_in[5];  // [M,D] = [3072,768]

    float* xb = (float*)d_out;

    float *g, *q, *k, *dq, *dk, *P, *r, *acc;
    cudaGetSymbolAddress((void**)&g,   d_g);
    cudaGetSymbolAddress((void**)&q,   d_q);
    cudaGetSymbolAddress((void**)&k,   d_k);
    cudaGetSymbolAddress((void**)&dq,  d_dq);
    cudaGetSymbolAddress((void**)&dk,  d_dk);
    cudaGetSymbolAddress((void**)&P,   d_P);
    cudaGetSymbolAddress((void**)&r,   d_r);
    cudaGetSymbolAddress((void**)&acc, d_acc);

    cudaMemcpyAsync(xb, x_in, (size_t)GSZ * sizeof(float), cudaMemcpyDeviceToDevice, 0);

    const long qOut = (long)NN * DD;     // per-batch stride into q/k/dq/dk
    const long qIn  = YY;                // per-head offset
    const long pOut = (long)HH * NN * NN;
    const long pIn  = (long)NN * NN;

    for (int step = 0; step < STEPS; step++) {
        layernorm_kernel<<<BN_TOK, 256>>>(xb, gamma, betaL, g);

        // q = g @ Wq^T ; k = g @ Wk^T     [8192 x 768 x 768]
        sgemm<true, false><<<dim3(DD/64, BN_TOK/64, 1), 256>>>(
            g, Wq, q, BN_TOK, DD, DD, DD, 1, 1, DD, DD,
            1, 0, 0, 0, 0, 0, 0, 1.f, 0, 0);
        sgemm<true, false><<<dim3(DD/64, BN_TOK/64, 1), 256>>>(
            g, Wk, k, BN_TOK, DD, DD, DD, 1, 1, DD, DD,
            1, 0, 0, 0, 0, 0, 0, 1.f, 0, 0);

        // S'[z][qi][ki] = beta * q . k      [1024 x 1024 x 64] x96
        sgemm<true, false><<<dim3(NN/64, NN/64, BB*HH), 256>>>(
            q, k, P, NN, NN, YY, DD, 1, 1, DD, NN,
            HH, qOut, qIn, qOut, qIn, pOut, pIn, BETA_ATT, 0, 0);

        softmax_kernel<<<BB*HH*NN, 256>>>(P);

        // dq = P' @ K      [1024 x 64 x 1024] x96
        sgemm<true, true><<<dim3(YY/64, NN/64, BB*HH), 256>>>(
            P, k, dq, NN, YY, NN, NN, 1, DD, 1, DD,
            HH, pOut, pIn, qOut, qIn, qOut, qIn, 1.f, 0, 0);

        // dkv = P'^T @ Q   [1024 x 64 x 1024] x96
        //   A(m,k) = P[k*NN + m]  -> sa_m=1, sa_k=NN (m-contiguous: AKC=false)
        //   B(k,n) = q[k*DD + n]  -> sb_k=DD, sb_n=1 (n-contiguous: BNC=true)
        sgemm<false, true><<<dim3(YY/64, NN/64, BB*HH), 256>>>(
            P, q, dk, NN, YY, NN, 1, NN, DD, 1, DD,
            HH, pOut, pIn, qOut, qIn, qOut, qIn, 1.f, 0, 0);

        // acc = dq @ Wq    [8192 x 768 x 768]
        sgemm<true, true><<<dim3(DD/64, BN_TOK/64, 1), 256>>>(
            dq, Wq, acc, BN_TOK, DD, DD, DD, 1, DD, 1, DD,
            1, 0, 0, 0, 0, 0, 0, 1.f, 0, 0);
        // acc += dkv @ Wk
        sgemm<true, true><<<dim3(DD/64, BN_TOK/64, 1), 256>>>(
            dk, Wk, acc, BN_TOK, DD, DD, DD, 1, DD, 1, DD,
            1, 0, 0, 0, 0, 0, 0, 1.f, 0, 1);

        // r = relu(g @ xi^T)   [8192 x 3072 x 768]
        sgemm<true, false><<<dim3(MM/64, BN_TOK/64, 1), 256>>>(
            g, xi, r, BN_TOK, MM, DD, DD, 1, 1, DD, MM,
            1, 0, 0, 0, 0, 0, 0, 1.f, 1, 0);
        // acc += r @ xi        [8192 x 768 x 3072]
        sgemm<true, true><<<dim3(DD/64, BN_TOK/64, 1), 256>>>(
            r, xi, acc, BN_TOK, DD, MM, MM, 1, DD, 1, DD,
            1, 0, 0, 0, 0, 0, 0, 1.f, 0, 1);

        update_kernel<<<GSZ / 256, 256>>>(xb, acc);
    }
}

// round 6
// speedup vs baseline: 2.2914x; 2.2914x over previous
#include <cuda_runtime.h>
#include <cstdint>
#include <math.h>

// Problem constants
#define BB 8
#define NN 1024
#define DD 768
#define HH 12
#define YY 64
#define MM 3072
#define STEPS 12
#define ALPHA 0.1f
#define EPS_LN 1e-5f
#define BETA_ATT 0.125f   // 1/sqrt(64)

#define BN_TOK (BB*NN)             // 8192
#define GSZ    (BB*NN*DD)          // 6291456
#define PSZ    ((long)BB*HH*NN*NN) // 100663296
#define RSZ    (BB*NN*MM)          // 25165824

// Scratch (static __device__ arrays: sanctioned alloc-free workaround)
__device__ float d_g[GSZ];
__device__ float d_q[GSZ];
__device__ float d_k[GSZ];
__device__ float d_dq[GSZ];
__device__ float d_dk[GSZ];
__device__ float d_acc[GSZ];
__device__ float d_r[RSZ];
__device__ float d_P[PSZ];

// ===========================================================================
// tf32 helpers
// ===========================================================================
__device__ __forceinline__ uint32_t f2tf32(float f) {
    uint32_t r;
    asm("cvt.rna.tf32.f32 %0, %1;" : "=r"(r) : "f"(f));
    return r;
}

__device__ __forceinline__ void mma_tf32(float* c, const uint32_t* a, const uint32_t* b) {
    asm volatile(
        "mma.sync.aligned.m16n8k8.row.col.f32.tf32.tf32.f32 "
        "{%0,%1,%2,%3}, {%4,%5,%6,%7}, {%8,%9}, {%0,%1,%2,%3};"
        : "+f"(c[0]), "+f"(c[1]), "+f"(c[2]), "+f"(c[3])
        : "r"(a[0]), "r"(a[1]), "r"(a[2]), "r"(a[3]), "r"(b[0]), "r"(b[1]));
}

// ===========================================================================
// Stage a [R x 16] fp32 tile into padded smem [R][17] as tf32.
//   element (i, j) = src[(r0+i)*srow + (k0+j)*scol]
//   scol==1: coalesced along k;  else: coalesced along rows (transpose stage,
//   conflict-free STS thanks to the odd 17-word pitch).
// ===========================================================================
template<int R, int RSH>
__device__ __forceinline__ void stage16(uint32_t* dst, const float* __restrict__ src,
                                        int r0, int k0, long srow, long scol, int t)
{
    if (scol == 1) {
#pragma unroll
        for (int p = 0; p < R / 16; p++) {
            int idx = t + p * 256;
            int i = idx >> 4, j = idx & 15;
            dst[i * 17 + j] = f2tf32(src[(long)(r0 + i) * srow + (k0 + j)]);
        }
    } else {
#pragma unroll
        for (int p = 0; p < R / 16; p++) {
            int idx = t + p * 256;
            int i = idx & (R - 1), j = idx >> RSH;
            dst[i * 17 + j] = f2tf32(src[(long)(r0 + i) + (long)(k0 + j) * scol]);
        }
    }
}

// ===========================================================================
// Generic strided-batched tf32 mma.sync GEMM.
//   C[m,n] = (accum?C:0) + scale * sum_k A(m,k)*B(n,k)   (+optional relu)
//   Block tile 128 x NTILE, 8 warps (2x4), warp tile 64 x NTILE/4.
// ===========================================================================
template<int NTILE>
__global__ __launch_bounds__(256)
void mmagemm(const float* __restrict__ Ag, const float* __restrict__ Bg,
             float* __restrict__ Cg, int Kdim,
             long sa_m, long sa_k, long sb_n, long sb_k, long sc,
             int bdiv, long aOut, long aIn, long bOut, long bIn, long cOut, long cIn,
             float scale, int relu, int accum)
{
    __shared__ uint32_t As[128 * 17];
    __shared__ uint32_t Bs[NTILE * 17];

    const int t = threadIdx.x, wid = t >> 5, lane = t & 31;
    const int wm = wid & 1, wn = wid >> 1;        // 2 x 4 warp grid
    constexpr int WN = NTILE / 4;                 // warp n-extent (32 or 16)
    constexpr int NT = WN / 8;                    // n8 tiles per warp (4 or 2)

    const int z = blockIdx.z;
    const float* A = Ag + (long)(z / bdiv) * aOut + (long)(z % bdiv) * aIn;
    const float* B = Bg + (long)(z / bdiv) * bOut + (long)(z % bdiv) * bIn;
    float*       C = Cg + (long)(z / bdiv) * cOut + (long)(z % bdiv) * cIn;
    const int m0 = blockIdx.y * 128;
    const int n0 = blockIdx.x * NTILE;

    float acc[4][NT][4];
#pragma unroll
    for (int i = 0; i < 4; i++)
#pragma unroll
        for (int j = 0; j < NT; j++)
#pragma unroll
            for (int e = 0; e < 4; e++) acc[i][j][e] = 0.f;

    const int qr = lane >> 2;        // 0..7
    const int qc = lane & 3;         // 0..3

    for (int k0 = 0; k0 < Kdim; k0 += 16) {
        stage16<128, 7>(As, A, m0, k0, sa_m, sa_k, t);
        stage16<NTILE, (NTILE == 128 ? 7 : 6)>(Bs, B, n0, k0, sb_n, sb_k, t);
        __syncthreads();

#pragma unroll
        for (int ks = 0; ks < 16; ks += 8) {
            uint32_t af[4][4];
#pragma unroll
            for (int mt = 0; mt < 4; mt++) {
                int r = wm * 64 + mt * 16 + qr;
                int cc = ks + qc;
                af[mt][0] = As[r * 17 + cc];
                af[mt][1] = As[(r + 8) * 17 + cc];
                af[mt][2] = As[r * 17 + cc + 4];
                af[mt][3] = As[(r + 8) * 17 + cc + 4];
            }
            uint32_t bf[NT][2];
#pragma unroll
            for (int nt = 0; nt < NT; nt++) {
                int bn = wn * WN + nt * 8 + qr;
                bf[nt][0] = Bs[bn * 17 + ks + qc];
                bf[nt][1] = Bs[bn * 17 + ks + qc + 4];
            }
#pragma unroll
            for (int mt = 0; mt < 4; mt++)
#pragma unroll
                for (int nt = 0; nt < NT; nt++)
                    mma_tf32(acc[mt][nt], af[mt], bf[nt]);
        }
        __syncthreads();
    }

    // Epilogue: fragment -> global (float2 per store), fused scale/relu/accum
#pragma unroll
    for (int mt = 0; mt < 4; mt++) {
        int row = m0 + wm * 64 + mt * 16 + qr;
#pragma unroll
        for (int nt = 0; nt < NT; nt++) {
            int col = n0 + wn * WN + nt * 8 + (qc << 1);
#pragma unroll
            for (int h = 0; h < 2; h++) {
                long idx = (long)(row + 8 * h) * sc + col;
                float v0 = acc[mt][nt][2 * h + 0] * scale;
                float v1 = acc[mt][nt][2 * h + 1] * scale;
                if (accum) {
                    float2 o = *(const float2*)&C[idx];
                    v0 += o.x; v1 += o.y;
                }
                if (relu) { v0 = fmaxf(v0, 0.f); v1 = fmaxf(v1, 0.f); }
                float2 w; w.x = v0; w.y = v1;
                *(float2*)&C[idx] = w;
            }
        }
    }
}

// ===========================================================================
// LayerNorm (one block per token row)
// ===========================================================================
__global__ __launch_bounds__(256)
void layernorm_kernel(const float* __restrict__ x, const float* __restrict__ gamma,
                      const float* __restrict__ beta, float* __restrict__ g)
{
    const long base = (long)blockIdx.x * DD;
    const int t = threadIdx.x;
    float v[3];
    float s = 0.f, ss = 0.f;
#pragma unroll
    for (int i = 0; i < 3; i++) {
        v[i] = x[base + t + i * 256];
        s += v[i];
        ss = fmaf(v[i], v[i], ss);
    }
#pragma unroll
    for (int o = 16; o > 0; o >>= 1) {
        s  += __shfl_xor_sync(0xffffffffu, s, o);
        ss += __shfl_xor_sync(0xffffffffu, ss, o);
    }
    __shared__ float rs[8], rss[8], bc[2];
    if ((t & 31) == 0) { rs[t >> 5] = s; rss[t >> 5] = ss; }
    __syncthreads();
    if (t == 0) {
        float a = 0.f, b = 0.f;
#pragma unroll
        for (int i = 0; i < 8; i++) { a += rs[i]; b += rss[i]; }
        float mean = a * (1.f / DD);
        float var  = b * (1.f / DD) - mean * mean;
        bc[0] = mean;
        bc[1] = rsqrtf(var + EPS_LN);
    }
    __syncthreads();
    const float mean = bc[0], rinv = bc[1];
#pragma unroll
    for (int i = 0; i < 3; i++) {
        int col = t + i * 256;
        g[base + col] = gamma[col] * (v[i] - mean) * rinv + beta[col];
    }
}

// ===========================================================================
// Row softmax over keys (row length 1024), in place
// ===========================================================================
__global__ __launch_bounds__(256)
void softmax_kernel(float* __restrict__ P)
{
    const long base = (long)blockIdx.x * NN;
    const int t = threadIdx.x;
    float v[4];
#pragma unroll
    for (int i = 0; i < 4; i++) v[i] = P[base + t + i * 256];
    float m = fmaxf(fmaxf(v[0], v[1]), fmaxf(v[2], v[3]));
#pragma unroll
    for (int o = 16; o > 0; o >>= 1) m = fmaxf(m, __shfl_xor_sync(0xffffffffu, m, o));
    __shared__ float rm[8], rsum[8], bc[2];
    if ((t & 31) == 0) rm[t >> 5] = m;
    __syncthreads();
    if (t == 0) {
        float mm = rm[0];
#pragma unroll
        for (int i = 1; i < 8; i++) mm = fmaxf(mm, rm[i]);
        bc[0] = mm;
    }
    __syncthreads();
    const float rowmax = bc[0];
    float s = 0.f;
#pragma unroll
    for (int i = 0; i < 4; i++) { v[i] = __expf(v[i] - rowmax); s += v[i]; }
#pragma unroll
    for (int o = 16; o > 0; o >>= 1) s += __shfl_xor_sync(0xffffffffu, s, o);
    if ((t & 31) == 0) rsum[t >> 5] = s;
    __syncthreads();
    if (t == 0) {
        float a = 0.f;
#pragma unroll
        for (int i = 0; i < 8; i++) a += rsum[i];
        bc[1] = 1.f / a;
    }
    __syncthreads();
    const float inv = bc[1];
#pragma unroll
    for (int i = 0; i < 4; i++) P[base + t + i * 256] = v[i] * inv;
}

__global__ __launch_bounds__(256)
void update_kernel(float* __restrict__ x, const float* __restrict__ acc)
{
    long i = (long)blockIdx.x * 256 + threadIdx.x;
    x[i] = fmaf(ALPHA, acc[i], x[i]);
}

// ===========================================================================
// Host
// ===========================================================================
static void tc(const float* A, const float* B, float* C, int M, int N, int K,
               long sam, long sak, long sbn, long sbk, long sc,
               int bdiv, long aO, long aI, long bO, long bI, long cO, long cI,
               float scale, int relu, int accum, int zcnt)
{
    if (N % 128 == 0) {
        dim3 grid(N / 128, M / 128, zcnt);
        mmagemm<128><<<grid, 256>>>(A, B, C, K, sam, sak, sbn, sbk, sc,
                                    bdiv, aO, aI, bO, bI, cO, cI,
                                    scale, relu, accum);
    } else {
        dim3 grid(N / 64, M / 128, zcnt);
        mmagemm<64><<<grid, 256>>>(A, B, C, K, sam, sak, sbn, sbk, sc,
                                   bdiv, aO, aI, bO, bI, cO, cI,
                                   scale, relu, accum);
    }
}

extern "C" void kernel_launch(void* const* d_in, const int* in_sizes, int n_in,
                              void* d_out, int out_size)
{
    const float* x_in  = (const float*)d_in[0];
    const float* gamma = (const float*)d_in[1];
    const float* betaL = (const float*)d_in[2];
    const float* Wq    = (const float*)d_in[3];  // [H*Y, D] row-major
    const float* Wk    = (const float*)d_in[4];
    const float* xi    = (const float*)d_in[5];  // [M, D]

    float* xb = (float*)d_out;

    float *g, *q, *k, *dq, *dk, *P, *r, *acc;
    cudaGetSymbolAddress((void**)&g,   d_g);
    cudaGetSymbolAddress((void**)&q,   d_q);
    cudaGetSymbolAddress((void**)&k,   d_k);
    cudaGetSymbolAddress((void**)&dq,  d_dq);
    cudaGetSymbolAddress((void**)&dk,  d_dk);
    cudaGetSymbolAddress((void**)&P,   d_P);
    cudaGetSymbolAddress((void**)&r,   d_r);
    cudaGetSymbolAddress((void**)&acc, d_acc);

    cudaMemcpyAsync(xb, x_in, (size_t)GSZ * sizeof(float), cudaMemcpyDeviceToDevice, 0);

    const long qOut = (long)NN * DD;
    const long qIn  = YY;
    const long pOut = (long)HH * NN * NN;
    const long pIn  = (long)NN * NN;

    for (int step = 0; step < STEPS; step++) {
        layernorm_kernel<<<BN_TOK, 256>>>(xb, gamma, betaL, g);

        // q = g @ Wq^T ; k = g @ Wk^T    [8192, 768] x [768(n), 768(k)]
        tc(g, Wq, q, BN_TOK, DD, DD, DD, 1, DD, 1, DD,
           1, 0, 0, 0, 0, 0, 0, 1.f, 0, 0, 1);
        tc(g, Wk, k, BN_TOK, DD, DD, DD, 1, DD, 1, DD,
           1, 0, 0, 0, 0, 0, 0, 1.f, 0, 0, 1);

        // P[q,key] = beta * q.k per (b,h):  M=N=1024, K=64
        tc(q, k, P, NN, NN, YY, DD, 1, DD, 1, NN,
           HH, qOut, qIn, qOut, qIn, pOut, pIn, BETA_ATT, 0, 0, BB * HH);

        softmax_kernel<<<BB * HH * NN, 256>>>(P);

        // dq = P' @ K:  A=P (K-major over keys), B(n=y,k=key)=k[k*DD+n]
        tc(P, k, dq, NN, YY, NN, NN, 1, 1, DD, DD,
           HH, pOut, pIn, qOut, qIn, qOut, qIn, 1.f, 0, 0, BB * HH);

        // dkv = P'^T @ Q:  A(m=key,k=q)=P[k*NN+m], B(n=y,k=q)=q[k*DD+n]
        tc(P, q, dk, NN, YY, NN, 1, NN, 1, DD, DD,
           HH, pOut, pIn, qOut, qIn, qOut, qIn, 1.f, 0, 0, BB * HH);

        // acc = dq @ Wq:  B(n=d, k=hy) = Wq[k*DD+n]
        tc(dq, Wq, acc, BN_TOK, DD, DD, DD, 1, 1, DD, DD,
           1, 0, 0, 0, 0, 0, 0, 1.f, 0, 0, 1);
        // acc += dkv @ Wk
        tc(dk, Wk, acc, BN_TOK, DD, DD, DD, 1, 1, DD, DD,
           1, 0, 0, 0, 0, 0, 0, 1.f, 0, 1, 1);

        // r = relu(g @ xi^T):  [8192, 3072], B(n=mem,k=d)=xi[n*DD+k]
        tc(g, xi, r, BN_TOK, MM, DD, DD, 1, DD, 1, MM,
           1, 0, 0, 0, 0, 0, 0, 1.f, 1, 0, 1);
        // acc += r @ xi:  B(n=d,k=mem)=xi[k*DD+n]
        tc(r, xi, acc, BN_TOK, DD, MM, MM, 1, 1, DD, DD,
           1, 0, 0, 0, 0, 0, 0, 1.f, 0, 1, 1);

        update_kernel<<<GSZ / 256, 256>>>(xb, acc);
    }
}

// round 8
// speedup vs baseline: 4.5725x; 1.9955x over previous
#include <cuda_runtime.h>
#include <cstdint>
#include <math.h>

// Problem constants
#define BB 8
#define NN 1024
#define DD 768
#define HH 12
#define YY 64
#define MM 3072
#define STEPS 12
#define ALPHA 0.1f
#define EPS_LN 1e-5f
#define BETA_ATT 0.125f   // 1/sqrt(64)

#define BN_TOK (BB*NN)             // 8192
#define GSZ    (BB*NN*DD)          // 6291456
#define PSZ    ((long)BB*HH*NN*NN) // 100663296
#define RSZ    (BB*NN*MM)          // 25165824

// Scratch (static __device__ arrays: sanctioned alloc-free workaround)
__device__ float d_g[GSZ];
__device__ float d_q[GSZ];
__device__ float d_k[GSZ];
__device__ float d_dq[GSZ];
__device__ float d_dk[GSZ];
__device__ float d_acc[GSZ];
__device__ float d_r[RSZ];
__device__ float d_P[PSZ];

// ===========================================================================
// helpers
// ===========================================================================
__device__ __forceinline__ uint32_t smem_u32(const void* p) {
    uint32_t a;
    asm("{ .reg .u64 t; cvta.to.shared.u64 t, %1; cvt.u32.u64 %0, t; }"
        : "=r"(a) : "l"(p));
    return a;
}
__device__ __forceinline__ uint32_t f2tf32(float f) {
    uint32_t r;
    asm("cvt.rna.tf32.f32 %0, %1;" : "=r"(r) : "f"(f));
    return r;
}
__device__ __forceinline__ void mma_tf32(float* c, const uint32_t* a, const uint32_t* b) {
    asm volatile(
        "mma.sync.aligned.m16n8k8.row.col.f32.tf32.tf32.f32 "
        "{%0,%1,%2,%3}, {%4,%5,%6,%7}, {%8,%9}, {%0,%1,%2,%3};"
        : "+f"(c[0]), "+f"(c[1]), "+f"(c[2]), "+f"(c[3])
        : "r"(a[0]), "r"(a[1]), "r"(a[2]), "r"(a[3]), "r"(b[0]), "r"(b[1]));
}
__device__ __forceinline__ void cp_async16(uint32_t dst, const void* src) {
    asm volatile("cp.async.cg.shared.global [%0], [%1], 16;" :: "r"(dst), "l"(src));
}
__device__ __forceinline__ void cp_async4(uint32_t dst, const void* src) {
    asm volatile("cp.async.ca.shared.global [%0], [%1], 4;" :: "r"(dst), "l"(src));
}
#define CP_COMMIT() asm volatile("cp.async.commit_group;" ::: "memory")
#define CP_WAIT1()  asm volatile("cp.async.wait_group 1;" ::: "memory")

#define PITCH 36   // words per smem row (144B: 16B-aligned, conflict-free frags)

// ===========================================================================
// Stage a [R x 32] fp32 tile (raw) into smem rows of PITCH words via cp.async.
//   element (i, j) = src[(r0+i)*srow + (k0+j)*scol]
//   scol==1: 16B vector copies.  else: per-element 4B copies (transposed).
// ===========================================================================
template<int R, int RSH>
__device__ __forceinline__ void stage32(uint32_t dstu, const float* __restrict__ src,
                                        int r0, int k0, long srow, long scol, int t)
{
    if (scol == 1) {
#pragma unroll
        for (int p = 0; p < R / 32; p++) {          // R*8/256 16B chunks
            int c = t + p * 256;
            int i = c >> 3, jc = c & 7;
            cp_async16(dstu + (uint32_t)(i * PITCH + 4 * jc) * 4,
                       src + (long)(r0 + i) * srow + k0 + 4 * jc);
        }
    } else {
#pragma unroll
        for (int p = 0; p < R / 8; p++) {           // R*32/256 elements
            int idx = t + p * 256;
            int i = idx & (R - 1), j = idx >> RSH;
            cp_async4(dstu + (uint32_t)(i * PITCH + j) * 4,
                      src + (long)(r0 + i) + (long)(k0 + j) * scol);
        }
    }
}

// ===========================================================================
// Generic strided-batched tf32 mma.sync GEMM, cp.async double-buffered K=32.
//   C[m,n] = (accum?C:0) + scale * sum_k A(m,k)*B(n,k)   (+optional relu)
//   Block tile 128 x NTILE, 8 warps (2x4), warp tile 64 x NTILE/4.
// ===========================================================================
template<int NTILE>
__global__ __launch_bounds__(256, 2)
void mmagemm(const float* __restrict__ Ag, const float* __restrict__ Bg,
             float* __restrict__ Cg, int Kdim,
             long sa_m, long sa_k, long sb_n, long sb_k, long sc,
             int bdiv, long aOut, long aIn, long bOut, long bIn, long cOut, long cIn,
             float scale, int relu, int accum)
{
    extern __shared__ uint32_t sm[];
    constexpr int AW = 128 * PITCH;       // words per A buffer
    constexpr int BW = NTILE * PITCH;
    uint32_t* Abuf[2] = { sm, sm + AW };
    uint32_t* Bbuf[2] = { sm + 2 * AW, sm + 2 * AW + BW };
    const uint32_t smu = smem_u32(sm);
    const uint32_t Au[2] = { smu, smu + AW * 4 };
    const uint32_t Bu[2] = { smu + 2 * AW * 4, smu + (2 * AW + BW) * 4 };

    const int t = threadIdx.x, lane = t & 31, wid = t >> 5;
    const int wm = wid & 1, wn = wid >> 1;        // 2 x 4 warp grid
    constexpr int WN = NTILE / 4;
    constexpr int NT = WN / 8;

    const int z = blockIdx.z;
    const float* A = Ag + (long)(z / bdiv) * aOut + (long)(z % bdiv) * aIn;
    const float* B = Bg + (long)(z / bdiv) * bOut + (long)(z % bdiv) * bIn;
    float*       C = Cg + (long)(z / bdiv) * cOut + (long)(z % bdiv) * cIn;
    const int m0 = blockIdx.y * 128;
    const int n0 = blockIdx.x * NTILE;

    float acc[4][NT][4];
#pragma unroll
    for (int i = 0; i < 4; i++)
#pragma unroll
        for (int j = 0; j < NT; j++)
#pragma unroll
            for (int e = 0; e < 4; e++) acc[i][j][e] = 0.f;

    const int qr = lane >> 2;   // 0..7
    const int qc = lane & 3;    // 0..3

    const int CH = Kdim >> 5;

    // prologue: stage chunk 0
    stage32<128, 7>(Au[0], A, m0, 0, sa_m, sa_k, t);
    stage32<NTILE, (NTILE == 128 ? 7 : 6)>(Bu[0], B, n0, 0, sb_n, sb_k, t);
    CP_COMMIT();

    for (int c = 0; c < CH; c++) {
        const int buf = c & 1;
        if (c + 1 < CH) {
            stage32<128, 7>(Au[buf ^ 1], A, m0, (c + 1) * 32, sa_m, sa_k, t);
            stage32<NTILE, (NTILE == 128 ? 7 : 6)>(Bu[buf ^ 1], B, n0, (c + 1) * 32,
                                                   sb_n, sb_k, t);
        }
        CP_COMMIT();
        CP_WAIT1();               // chunk c resident
        __syncthreads();

        const uint32_t* As = Abuf[buf];
        const uint32_t* Bs = Bbuf[buf];
#pragma unroll
        for (int ks = 0; ks < 32; ks += 8) {
            uint32_t af[4][4];
#pragma unroll
            for (int mt = 0; mt < 4; mt++) {
                int r = wm * 64 + mt * 16 + qr;
                int cc = ks + qc;
                af[mt][0] = f2tf32(__uint_as_float(As[r * PITCH + cc]));
                af[mt][1] = f2tf32(__uint_as_float(As[(r + 8) * PITCH + cc]));
                af[mt][2] = f2tf32(__uint_as_float(As[r * PITCH + cc + 4]));
                af[mt][3] = f2tf32(__uint_as_float(As[(r + 8) * PITCH + cc + 4]));
            }
            uint32_t bf[NT][2];
#pragma unroll
            for (int nt = 0; nt < NT; nt++) {
                int bn = wn * WN + nt * 8 + qr;
                bf[nt][0] = f2tf32(__uint_as_float(Bs[bn * PITCH + ks + qc]));
                bf[nt][1] = f2tf32(__uint_as_float(Bs[bn * PITCH + ks + qc + 4]));
            }
#pragma unroll
            for (int mt = 0; mt < 4; mt++)
#pragma unroll
                for (int nt = 0; nt < NT; nt++)
                    mma_tf32(acc[mt][nt], af[mt], bf[nt]);
        }
        __syncthreads();          // buffer c free for re-staging at c+2
    }

    // Epilogue: fragment -> global (float2), fused scale/relu/accum
#pragma unroll
    for (int mt = 0; mt < 4; mt++) {
        int row = m0 + wm * 64 + mt * 16 + qr;
#pragma unroll
        for (int nt = 0; nt < NT; nt++) {
            int col = n0 + wn * WN + nt * 8 + (qc << 1);
#pragma unroll
            for (int h = 0; h < 2; h++) {
                long idx = (long)(row + 8 * h) * sc + col;
                float v0 = acc[mt][nt][2 * h + 0] * scale;
                float v1 = acc[mt][nt][2 * h + 1] * scale;
                if (accum) {
                    float2 o = *(const float2*)&C[idx];
                    v0 += o.x; v1 += o.y;
                }
                if (relu) { v0 = fmaxf(v0, 0.f); v1 = fmaxf(v1, 0.f); }
                float2 w; w.x = v0; w.y = v1;
                *(float2*)&C[idx] = w;
            }
        }
    }
}

// ===========================================================================
// LayerNorm (one block per token row)
// ===========================================================================
__global__ __launch_bounds__(256)
void layernorm_kernel(const float* __restrict__ x, const float* __restrict__ gamma,
                      const float* __restrict__ beta, float* __restrict__ g)
{
    const long base = (long)blockIdx.x * DD;
    const int t = threadIdx.x;
    float v[3];
    float s = 0.f, ss = 0.f;
#pragma unroll
    for (int i = 0; i < 3; i++) {
        v[i] = x[base + t + i * 256];
        s += v[i];
        ss = fmaf(v[i], v[i], ss);
    }
#pragma unroll
    for (int o = 16; o > 0; o >>= 1) {
        s  += __shfl_xor_sync(0xffffffffu, s, o);
        ss += __shfl_xor_sync(0xffffffffu, ss, o);
    }
    __shared__ float rs[8], rss[8], bc[2];
    if ((t & 31) == 0) { rs[t >> 5] = s; rss[t >> 5] = ss; }
    __syncthreads();
    if (t == 0) {
        float a = 0.f, b = 0.f;
#pragma unroll
        for (int i = 0; i < 8; i++) { a += rs[i]; b += rss[i]; }
        float mean = a * (1.f / DD);
        float var  = b * (1.f / DD) - mean * mean;
        bc[0] = mean;
        bc[1] = rsqrtf(var + EPS_LN);
    }
    __syncthreads();
    const float mean = bc[0], rinv = bc[1];
#pragma unroll
    for (int i = 0; i < 3; i++) {
        int col = t + i * 256;
        g[base + col] = gamma[col] * (v[i] - mean) * rinv + beta[col];
    }
}

// ===========================================================================
// Row softmax over keys (row length 1024), in place
// ===========================================================================
__global__ __launch_bounds__(256)
void softmax_kernel(float* __restrict__ P)
{
    const long base = (long)blockIdx.x * NN;
    const int t = threadIdx.x;
    float v[4];
#pragma unroll
    for (int i = 0; i < 4; i++) v[i] = P[base + t + i * 256];
    float m = fmaxf(fmaxf(v[0], v[1]), fmaxf(v[2], v[3]));
#pragma unroll
    for (int o = 16; o > 0; o >>= 1) m = fmaxf(m, __shfl_xor_sync(0xffffffffu, m, o));
    __shared__ float rm[8], rsum[8], bc[2];
    if ((t & 31) == 0) rm[t >> 5] = m;
    __syncthreads();
    if (t == 0) {
        float mm = rm[0];
#pragma unroll
        for (int i = 1; i < 8; i++) mm = fmaxf(mm, rm[i]);
        bc[0] = mm;
    }
    __syncthreads();
    const float rowmax = bc[0];
    float s = 0.f;
#pragma unroll
    for (int i = 0; i < 4; i++) { v[i] = __expf(v[i] - rowmax); s += v[i]; }
#pragma unroll
    for (int o = 16; o > 0; o >>= 1) s += __shfl_xor_sync(0xffffffffu, s, o);
    if ((t & 31) == 0) rsum[t >> 5] = s;
    __syncthreads();
    if (t == 0) {
        float a = 0.f;
#pragma unroll
        for (int i = 0; i < 8; i++) a += rsum[i];
        bc[1] = 1.f / a;
    }
    __syncthreads();
    const float inv = bc[1];
#pragma unroll
    for (int i = 0; i < 4; i++) P[base + t + i * 256] = v[i] * inv;
}

__global__ __launch_bounds__(256)
void update_kernel(float* __restrict__ x, const float* __restrict__ acc)
{
    long i = (long)blockIdx.x * 256 + threadIdx.x;
    x[i] = fmaf(ALPHA, acc[i], x[i]);
}

// ===========================================================================
// Host
// ===========================================================================
static const int SMEM128 = (2 * 128 * PITCH + 2 * 128 * PITCH) * 4;  // 73728
static const int SMEM64  = (2 * 128 * PITCH + 2 * 64  * PITCH) * 4;  // 55296

static void tc(const float* A, const float* B, float* C, int M, int N, int K,
               long sam, long sak, long sbn, long sbk, long sc,
               int bdiv, long aO, long aI, long bO, long bI, long cO, long cI,
               float scale, int relu, int accum, int zcnt)
{
    static bool init = false;
    if (!init) {
        cudaFuncSetAttribute(mmagemm<128>, cudaFuncAttributeMaxDynamicSharedMemorySize, SMEM128);
        cudaFuncSetAttribute(mmagemm<64>,  cudaFuncAttributeMaxDynamicSharedMemorySize, SMEM64);
        init = true;
    }
    if (N % 128 == 0) {
        dim3 grid(N / 128, M / 128, zcnt);
        mmagemm<128><<<grid, 256, SMEM128>>>(A, B, C, K, sam, sak, sbn, sbk, sc,
                                             bdiv, aO, aI, bO, bI, cO, cI,
                                             scale, relu, accum);
    } else {
        dim3 grid(N / 64, M / 128, zcnt);
        mmagemm<64><<<grid, 256, SMEM64>>>(A, B, C, K, sam, sak, sbn, sbk, sc,
                                           bdiv, aO, aI, bO, bI, cO, cI,
                                           scale, relu, accum);
    }
}

extern "C" void kernel_launch(void* const* d_in, const int* in_sizes, int n_in,
                              void* d_out, int out_size)
{
    const float* x_in  = (const float*)d_in[0];
    const float* gamma = (const float*)d_in[1];
    const float* betaL = (const float*)d_in[2];
    const float* Wq    = (const float*)d_in[3];  // [H*Y, D] row-major
    const float* Wk    = (const float*)d_in[4];
    const float* xi    = (const float*)d_in[5];  // [M, D]

    float* xb = (float*)d_out;

    float *g, *q, *k, *dq, *dk, *P, *r, *acc;
    cudaGetSymbolAddress((void**)&g,   d_g);
    cudaGetSymbolAddress((void**)&q,   d_q);
    cudaGetSymbolAddress((void**)&k,   d_k);
    cudaGetSymbolAddress((void**)&dq,  d_dq);
    cudaGetSymbolAddress((void**)&dk,  d_dk);
    cudaGetSymbolAddress((void**)&P,   d_P);
    cudaGetSymbolAddress((void**)&r,   d_r);
    cudaGetSymbolAddress((void**)&acc, d_acc);

    cudaMemcpyAsync(xb, x_in, (size_t)GSZ * sizeof(float), cudaMemcpyDeviceToDevice, 0);

    const long qOut = (long)NN * DD;
    const long qIn  = YY;
    const long pOut = (long)HH * NN * NN;
    const long pIn  = (long)NN * NN;

    for (int step = 0; step < STEPS; step++) {
        layernorm_kernel<<<BN_TOK, 256>>>(xb, gamma, betaL, g);

        // q = g @ Wq^T ; k = g @ Wk^T    [8192, 768] x [768(n), 768(k)]
        tc(g, Wq, q, BN_TOK, DD, DD, DD, 1, DD, 1, DD,
           1, 0, 0, 0, 0, 0, 0, 1.f, 0, 0, 1);
        tc(g, Wk, k, BN_TOK, DD, DD, DD, 1, DD, 1, DD,
           1, 0, 0, 0, 0, 0, 0, 1.f, 0, 0, 1);

        // P[q,key] = beta * q.k per (b,h):  M=N=1024, K=64
        tc(q, k, P, NN, NN, YY, DD, 1, DD, 1, NN,
           HH, qOut, qIn, qOut, qIn, pOut, pIn, BETA_ATT, 0, 0, BB * HH);

        softmax_kernel<<<BB * HH * NN, 256>>>(P);

        // dq = P' @ K:  A=P (key-contig), B(n=y,k=key)=k[k*DD+n] (transposed)
        tc(P, k, dq, NN, YY, NN, NN, 1, 1, DD, DD,
           HH, pOut, pIn, qOut, qIn, qOut, qIn, 1.f, 0, 0, BB * HH);

        // dkv = P'^T @ Q:  A(m=key,k=q)=P[k*NN+m] (transposed), B transposed
        tc(P, q, dk, NN, YY, NN, 1, NN, 1, DD, DD,
           HH, pOut, pIn, qOut, qIn, qOut, qIn, 1.f, 0, 0, BB * HH);

        // acc = dq @ Wq:  B(n=d, k=hy) = Wq[k*DD+n] (transposed)
        tc(dq, Wq, acc, BN_TOK, DD, DD, DD, 1, 1, DD, DD,
           1, 0, 0, 0, 0, 0, 0, 1.f, 0, 0, 1);
        // acc += dkv @ Wk
        tc(dk, Wk, acc, BN_TOK, DD, DD, DD, 1, 1, DD, DD,
           1, 0, 0, 0, 0, 0, 0, 1.f, 0, 1, 1);

        // r = relu(g @ xi^T):  [8192, 3072], B(n=mem,k=d)=xi[n*DD+k]
        tc(g, xi, r, BN_TOK, MM, DD, DD, 1, DD, 1, MM,
           1, 0, 0, 0, 0, 0, 0, 1.f, 1, 0, 1);
        // acc += r @ xi:  B(n=d,k=mem)=xi[k*DD+n] (transposed)
        tc(r, xi, acc, BN_TOK, DD, MM, MM, 1, 1, DD, DD,
           1, 0, 0, 0, 0, 0, 0, 1.f, 0, 1, 1);

        update_kernel<<<GSZ / 256, 256>>>(xb, acc);
    }
}